// round 7
// baseline (speedup 1.0000x reference)
#include <cuda_runtime.h>
#include <cstdint>

// MultiStepIFNode: T=16 integrate-and-fire, pure HBM streaming (256 MiB in,
// 256 MiB out). R1-R6 established: traffic is at the 512 MiB minimum and
// every SM-side supply/granularity config lands at 6.26-6.41 TB/s (~80% of
// HBM spec) — the mixed read/write DRAM ceiling.
//
// R7 (final probe): __stcs -> __stwt on the store path. Write-through
// pushes store traffic to DRAM eagerly in large same-direction bursts
// (per-CTA 16-store epilogues) instead of lazy L2 writeback drains that
// interleave with demand reads. Tests the turnaround theory from the
// write side. Config otherwise identical to the R5 best (81.98us):
// block=256, 16-load front batch, __ldcs reads.

static constexpr int T_STEPS = 16;

__global__ __launch_bounds__(256, 2) void if_multistep_kernel(
    const float4* __restrict__ x,   // T * n4 float4s
    float4* __restrict__ out,       // T * n4 float4s
    int n4)                         // float4s per timestep (N/4)
{
    int i = blockIdx.x * blockDim.x + threadIdx.x;
    if (i >= n4) return;

    // Front-batch all 16 loads: one contiguous read burst per thread
    // before any store issues.
    float4 xt[T_STEPS];
    #pragma unroll
    for (int t = 0; t < T_STEPS; t++) {
        xt[t] = __ldcs(&x[(size_t)t * n4 + i]);
    }

    float vx = 0.f, vy = 0.f, vz = 0.f, vw = 0.f;

    #pragma unroll
    for (int t = 0; t < T_STEPS; t++) {
        vx += xt[t].x;
        vy += xt[t].y;
        vz += xt[t].z;
        vw += xt[t].w;

        float4 s;
        s.x = (vx >= 1.0f) ? 1.0f : 0.0f;
        s.y = (vy >= 1.0f) ? 1.0f : 0.0f;
        s.z = (vz >= 1.0f) ? 1.0f : 0.0f;
        s.w = (vw >= 1.0f) ? 1.0f : 0.0f;

        vx -= s.x;
        vy -= s.y;
        vz -= s.z;
        vw -= s.w;

        __stwt(&out[(size_t)t * n4 + i], s);
    }
}

extern "C" void kernel_launch(void* const* d_in, const int* in_sizes, int n_in,
                              void* d_out, int out_size)
{
    const float4* x = (const float4*)d_in[0];
    float4* out = (float4*)d_out;

    int n_per_step = out_size / T_STEPS;   // 4,194,304
    int n4 = n_per_step / 4;               // 1,048,576

    const int threads = 256;
    int blocks = (n4 + threads - 1) / threads;   // 4096
    if_multistep_kernel<<<blocks, threads>>>(x, out, n4);
}

// round 8
// speedup vs baseline: 1.0198x; 1.0198x over previous
#include <cuda_runtime.h>
#include <cstdint>

// MultiStepIFNode: T=16 integrate-and-fire over (16, 32, 128, 32, 32) fp32.
// Per neuron: v += x[t]; spike = (v >= 1); v -= spike.
//
// FINAL (R5 config, best measured 81.98us dur / ~77us kernel, 6.4 TB/s):
// Pure HBM streaming at the provable traffic minimum (256 MiB in + 256 MiB
// out). The R1-R7 sweep tested occupancy 21-88%, per-thread MLP 2-16,
// persistent vs waved grids, block 128/256, r/w grouping 8/8 vs 16/16, and
// store policies default/__stcs/__stwt: all good configs land at
// 6.26-6.41 TB/s (~80% of 8 TB/s spec) — the mixed read/write DRAM
// scheduler ceiling (bus turnaround/refresh). Losers: persistent grid
// (-10%: starves chip-level load concurrency), __stwt (-2.5%: fragments
// the write stream into eager sectors).
//
// Structure: one thread owns 4 consecutive neurons (float4), front-batches
// all 16 timestep loads (one contiguous read burst, 16 outstanding
// LDG.128.CS), then runs the v-recurrence in registers and emits 16
// STG.128.CS. Loads are fully coalesced per timestep; data is touched
// exactly once so evict-first keeps L2 clean.

static constexpr int T_STEPS = 16;

__global__ __launch_bounds__(256, 2) void if_multistep_kernel(
    const float4* __restrict__ x,   // T * n4 float4s
    float4* __restrict__ out,       // T * n4 float4s
    int n4)                         // float4s per timestep (N/4)
{
    int i = blockIdx.x * blockDim.x + threadIdx.x;
    if (i >= n4) return;

    // Front-batch all 16 loads: one contiguous read burst per thread
    // before any store issues.
    float4 xt[T_STEPS];
    #pragma unroll
    for (int t = 0; t < T_STEPS; t++) {
        xt[t] = __ldcs(&x[(size_t)t * n4 + i]);
    }

    float vx = 0.f, vy = 0.f, vz = 0.f, vw = 0.f;

    #pragma unroll
    for (int t = 0; t < T_STEPS; t++) {
        vx += xt[t].x;
        vy += xt[t].y;
        vz += xt[t].z;
        vw += xt[t].w;

        float4 s;
        s.x = (vx >= 1.0f) ? 1.0f : 0.0f;
        s.y = (vy >= 1.0f) ? 1.0f : 0.0f;
        s.z = (vz >= 1.0f) ? 1.0f : 0.0f;
        s.w = (vw >= 1.0f) ? 1.0f : 0.0f;

        vx -= s.x;
        vy -= s.y;
        vz -= s.z;
        vw -= s.w;

        __stcs(&out[(size_t)t * n4 + i], s);
    }
}

extern "C" void kernel_launch(void* const* d_in, const int* in_sizes, int n_in,
                              void* d_out, int out_size)
{
    const float4* x = (const float4*)d_in[0];
    float4* out = (float4*)d_out;

    int n_per_step = out_size / T_STEPS;   // 4,194,304
    int n4 = n_per_step / 4;               // 1,048,576

    const int threads = 256;
    int blocks = (n4 + threads - 1) / threads;   // 4096
    if_multistep_kernel<<<blocks, threads>>>(x, out, n4);
}

// round 9
// speedup vs baseline: 1.0234x; 1.0035x over previous
#include <cuda_runtime.h>
#include <cstdint>

// MultiStepIFNode: T=16 integrate-and-fire over (16, 32, 128, 32, 32) fp32.
// Per neuron: v += x[t]; spike = (v >= 1); v -= spike.
//
// FINAL KERNEL (R5 config; best measured 81.98us dur / ~77us kernel at
// 6.4 TB/s). Pure HBM streaming at the provable traffic minimum (256 MiB
// in + 256 MiB out; measured BW x time == 2x tensor size, so zero wasted
// bytes). The R1-R8 sweep tested, two-sided:
//   supply side: occupancy 21-88%, per-thread MLP 2-16, persistent vs
//                waved grids, block 128/256  -> all within 2%
//   drain side:  store default / __stcs / __stwt -> __stcs best,
//                __stwt -2.5% (fragments write stream)
// Every sane config lands at 6.26-6.41 TB/s = ~79% of 8 TB/s spec: the
// mixed read/write DRAM scheduler ceiling (bus turnaround/refresh).
//
// Structure: one thread owns 4 consecutive neurons (float4), front-batches
// all 16 timestep loads (one contiguous read burst, 16 outstanding
// LDG.128.CS), runs the v-recurrence in registers, emits 16 STG.128.CS.
// Grid exactly covers n4 (1,048,576 = 4096 * 256) so no bounds guard.

static constexpr int T_STEPS = 16;

__global__ __launch_bounds__(256, 2) void if_multistep_kernel(
    const float4* __restrict__ x,   // T * n4 float4s
    float4* __restrict__ out,       // T * n4 float4s
    int n4)                         // float4s per timestep (N/4)
{
    const int i = blockIdx.x * blockDim.x + threadIdx.x;

    // Front-batch all 16 loads: one contiguous read burst per thread
    // before any store issues.
    float4 xt[T_STEPS];
    #pragma unroll
    for (int t = 0; t < T_STEPS; t++) {
        xt[t] = __ldcs(&x[(size_t)t * n4 + i]);
    }

    float vx = 0.f, vy = 0.f, vz = 0.f, vw = 0.f;

    #pragma unroll
    for (int t = 0; t < T_STEPS; t++) {
        vx += xt[t].x;
        vy += xt[t].y;
        vz += xt[t].z;
        vw += xt[t].w;

        float4 s;
        s.x = (vx >= 1.0f) ? 1.0f : 0.0f;
        s.y = (vy >= 1.0f) ? 1.0f : 0.0f;
        s.z = (vz >= 1.0f) ? 1.0f : 0.0f;
        s.w = (vw >= 1.0f) ? 1.0f : 0.0f;

        vx -= s.x;
        vy -= s.y;
        vz -= s.z;
        vw -= s.w;

        __stcs(&out[(size_t)t * n4 + i], s);
    }
}

extern "C" void kernel_launch(void* const* d_in, const int* in_sizes, int n_in,
                              void* d_out, int out_size)
{
    const float4* x = (const float4*)d_in[0];
    float4* out = (float4*)d_out;

    int n_per_step = out_size / T_STEPS;   // 4,194,304
    int n4 = n_per_step / 4;               // 1,048,576 (exact multiple of 4096*256)

    const int threads = 256;
    int blocks = n4 / threads;             // 4096, exact
    if_multistep_kernel<<<blocks, threads>>>(x, out, n4);
}